// round 2
// baseline (speedup 1.0000x reference)
#include <cuda_runtime.h>

// ---------------------------------------------------------------------------
// Problem constants
// ---------------------------------------------------------------------------
constexpr int S_LEN = 2048;
constexpr int BATCH = 2;
constexpr int EMB   = 512;
constexpr int HEADS = 8;
constexpr int HD    = 64;               // head dim
constexpr int NBH   = BATCH * HEADS;    // 16
constexpr int NTOK  = S_LEN * BATCH;    // 4096 rows for the final FC

// Scratch (device globals: no allocation allowed)
__device__ float g_Q[NBH * S_LEN * HD];
__device__ float g_K[NBH * S_LEN * HD];
__device__ float g_V[NBH * S_LEN * HD];
__device__ float g_Att[NBH * S_LEN * HD];

// ---------------------------------------------------------------------------
// Kernel A: QKV projection.  qh is a flat-contiguous [16][2048][64] view.
// y[bh][s][o] = sum_d x[bh][s][d] * W[o][d]   (torch Linear: x @ W.T)
// Q additionally scaled by 1/sqrt(64) = 0.125 (folds the softmax scale).
// grid: (S/64, 16, 3), block: 256
// ---------------------------------------------------------------------------
__global__ __launch_bounds__(256) void proj_kernel(
    const float* __restrict__ q, const float* __restrict__ k,
    const float* __restrict__ v,
    const float* __restrict__ Wq, const float* __restrict__ Wk,
    const float* __restrict__ Wv)
{
    __shared__ float Ws[HD * HD];       // [o][d]
    __shared__ float Xs[64][HD + 1];    // padded vs bank conflicts

    const float* in;  const float* W;  float* out;  float scale;
    int z = blockIdx.z;
    if (z == 0)      { in = q; W = Wq; out = g_Q; scale = 0.125f; }
    else if (z == 1) { in = k; W = Wk; out = g_K; scale = 1.0f; }
    else             { in = v; W = Wv; out = g_V; scale = 1.0f; }

    int bh = blockIdx.y;
    int r0 = blockIdx.x * 64;
    const float* inb  = in  + (size_t)bh * S_LEN * HD + (size_t)r0 * HD;
    float*       outb = out + (size_t)bh * S_LEN * HD + (size_t)r0 * HD;
    int tid = threadIdx.x;

    // Load W (4096 floats) and X tile (64x64), both contiguous in gmem.
    #pragma unroll
    for (int i = 0; i < 4; i++)
        ((float4*)Ws)[tid + i * 256] = ((const float4*)W)[tid + i * 256];
    #pragma unroll
    for (int i = 0; i < 4; i++) {
        int f4 = tid + i * 256;           // 0..1023
        int r  = f4 >> 4;
        int d0 = (f4 & 15) * 4;
        float4 val = ((const float4*)inb)[f4];
        Xs[r][d0 + 0] = val.x;  Xs[r][d0 + 1] = val.y;
        Xs[r][d0 + 2] = val.z;  Xs[r][d0 + 3] = val.w;
    }
    __syncthreads();

    int r  = tid & 63;
    int c0 = (tid >> 6) * 16;             // 4 groups of 16 output cols
    float acc[16];
    #pragma unroll
    for (int j = 0; j < 16; j++) acc[j] = 0.f;

    #pragma unroll 8
    for (int d = 0; d < HD; d++) {
        float xv = Xs[r][d];
        #pragma unroll
        for (int j = 0; j < 16; j++)
            acc[j] += xv * Ws[(c0 + j) * HD + d];   // broadcast LDS
    }

    #pragma unroll
    for (int j = 0; j < 16; j += 4) {
        float4 val = make_float4(acc[j] * scale, acc[j + 1] * scale,
                                 acc[j + 2] * scale, acc[j + 3] * scale);
        *(float4*)&outb[r * HD + c0 + j] = val;
    }
}

// ---------------------------------------------------------------------------
// Kernel B: flash attention per (bh), BM=64 query rows per block, BN=32 key
// tiles, 128 threads (tr 0..15, tc 0..7), 4x4 score microtile, 4x8 O microtile.
// Smem layouts transposed so fragments are float4 loads.
// grid: (S/64, 16), block: 128
// ---------------------------------------------------------------------------
constexpr int BM = 64;
constexpr int BN = 32;
constexpr int QS_STR = 68;   // [d][m], padded
constexpr int KS_STR = 36;   // [d][n], padded
constexpr int PS_STR = 68;   // [n][m], padded

__global__ __launch_bounds__(128) void flash_kernel()
{
    __shared__ float Qs[HD * QS_STR];    // 17408 B
    __shared__ float Ks[HD * KS_STR];    //  9216 B
    __shared__ float Vs[BN * HD];        //  8192 B  [n][d]
    __shared__ float Ps[BN * PS_STR];    //  8704 B  [n][m]

    int bh  = blockIdx.y;
    int m0  = blockIdx.x * BM;
    int tid = threadIdx.x;
    int tr  = tid >> 3;      // 0..15 -> 4 query rows each
    int tc  = tid & 7;       // 0..7

    const float* Qg = g_Q + (size_t)bh * S_LEN * HD + (size_t)m0 * HD;
    const float* Kg = g_K + (size_t)bh * S_LEN * HD;
    const float* Vg = g_V + (size_t)bh * S_LEN * HD;
    float*       Ag = g_Att + (size_t)bh * S_LEN * HD + (size_t)m0 * HD;

    // Load Q tile (64x64, contiguous) transposed into Qs[d][m].
    #pragma unroll
    for (int i = 0; i < 8; i++) {
        int f4 = tid + i * 128;          // 0..1023
        int r  = f4 >> 4;
        int d0 = (f4 & 15) * 4;
        float4 val = ((const float4*)Qg)[f4];
        Qs[(d0 + 0) * QS_STR + r] = val.x;
        Qs[(d0 + 1) * QS_STR + r] = val.y;
        Qs[(d0 + 2) * QS_STR + r] = val.z;
        Qs[(d0 + 3) * QS_STR + r] = val.w;
    }

    float o[4][8];
    float mrow[4], lrow[4];
    #pragma unroll
    for (int i = 0; i < 4; i++) {
        mrow[i] = -1e30f; lrow[i] = 0.f;
        #pragma unroll
        for (int j = 0; j < 8; j++) o[i][j] = 0.f;
    }

    for (int n0 = 0; n0 < S_LEN; n0 += BN) {
        __syncthreads();   // prior P@V done before overwriting Ks/Vs
        // K tile (32x64, contiguous) transposed into Ks[d][n]
        #pragma unroll
        for (int i = 0; i < 4; i++) {
            int f4 = tid + i * 128;       // 0..511
            int n  = f4 >> 4;
            int d0 = (f4 & 15) * 4;
            float4 val = ((const float4*)(Kg + (size_t)n0 * HD))[f4];
            Ks[(d0 + 0) * KS_STR + n] = val.x;
            Ks[(d0 + 1) * KS_STR + n] = val.y;
            Ks[(d0 + 2) * KS_STR + n] = val.z;
            Ks[(d0 + 3) * KS_STR + n] = val.w;
        }
        // V tile: straight copy [n][d]
        #pragma unroll
        for (int i = 0; i < 4; i++) {
            int f4 = tid + i * 128;
            ((float4*)Vs)[f4] = ((const float4*)(Vg + (size_t)n0 * HD))[f4];
        }
        __syncthreads();

        // S = Q K^T  (scale already folded into Q)
        float s[4][4];
        #pragma unroll
        for (int i = 0; i < 4; i++)
            #pragma unroll
            for (int j = 0; j < 4; j++) s[i][j] = 0.f;

        #pragma unroll 8
        for (int d = 0; d < HD; d++) {
            float4 qf = *(const float4*)&Qs[d * QS_STR + tr * 4];
            float4 kf = *(const float4*)&Ks[d * KS_STR + tc * 4];
            s[0][0] += qf.x * kf.x; s[0][1] += qf.x * kf.y;
            s[0][2] += qf.x * kf.z; s[0][3] += qf.x * kf.w;
            s[1][0] += qf.y * kf.x; s[1][1] += qf.y * kf.y;
            s[1][2] += qf.y * kf.z; s[1][3] += qf.y * kf.w;
            s[2][0] += qf.z * kf.x; s[2][1] += qf.z * kf.y;
            s[2][2] += qf.z * kf.z; s[2][3] += qf.z * kf.w;
            s[3][0] += qf.w * kf.x; s[3][1] += qf.w * kf.y;
            s[3][2] += qf.w * kf.z; s[3][3] += qf.w * kf.w;
        }

        // Online softmax (row groups = 8 lanes: tc bits 0..2)
        #pragma unroll
        for (int i = 0; i < 4; i++) {
            float mx = fmaxf(fmaxf(s[i][0], s[i][1]), fmaxf(s[i][2], s[i][3]));
            mx = fmaxf(mx, __shfl_xor_sync(0xffffffffu, mx, 1));
            mx = fmaxf(mx, __shfl_xor_sync(0xffffffffu, mx, 2));
            mx = fmaxf(mx, __shfl_xor_sync(0xffffffffu, mx, 4));
            float mnew = fmaxf(mrow[i], mx);
            float corr = __expf(mrow[i] - mnew);
            mrow[i] = mnew;
            float rs = 0.f;
            #pragma unroll
            for (int j = 0; j < 4; j++) {
                s[i][j] = __expf(s[i][j] - mnew);
                rs += s[i][j];
            }
            rs += __shfl_xor_sync(0xffffffffu, rs, 1);
            rs += __shfl_xor_sync(0xffffffffu, rs, 2);
            rs += __shfl_xor_sync(0xffffffffu, rs, 4);
            lrow[i] = lrow[i] * corr + rs;
            #pragma unroll
            for (int j = 0; j < 8; j++) o[i][j] *= corr;
        }

        // Store P transposed: Ps[n][m]
        #pragma unroll
        for (int j = 0; j < 4; j++)
            #pragma unroll
            for (int i = 0; i < 4; i++)
                Ps[(tc * 4 + j) * PS_STR + tr * 4 + i] = s[i][j];
        __syncthreads();

        // O += P V   (thread: 4 rows x 8 d-cols)
        #pragma unroll 4
        for (int n = 0; n < BN; n++) {
            float4 pf = *(const float4*)&Ps[n * PS_STR + tr * 4];
            float4 v0 = *(const float4*)&Vs[n * HD + tc * 8];
            float4 v1 = *(const float4*)&Vs[n * HD + tc * 8 + 4];
            o[0][0] += pf.x * v0.x; o[0][1] += pf.x * v0.y;
            o[0][2] += pf.x * v0.z; o[0][3] += pf.x * v0.w;
            o[0][4] += pf.x * v1.x; o[0][5] += pf.x * v1.y;
            o[0][6] += pf.x * v1.z; o[0][7] += pf.x * v1.w;
            o[1][0] += pf.y * v0.x; o[1][1] += pf.y * v0.y;
            o[1][2] += pf.y * v0.z; o[1][3] += pf.y * v0.w;
            o[1][4] += pf.y * v1.x; o[1][5] += pf.y * v1.y;
            o[1][6] += pf.y * v1.z; o[1][7] += pf.y * v1.w;
            o[2][0] += pf.z * v0.x; o[2][1] += pf.z * v0.y;
            o[2][2] += pf.z * v0.z; o[2][3] += pf.z * v0.w;
            o[2][4] += pf.z * v1.x; o[2][5] += pf.z * v1.y;
            o[2][6] += pf.z * v1.z; o[2][7] += pf.z * v1.w;
            o[3][0] += pf.w * v0.x; o[3][1] += pf.w * v0.y;
            o[3][2] += pf.w * v0.z; o[3][3] += pf.w * v0.w;
            o[3][4] += pf.w * v1.x; o[3][5] += pf.w * v1.y;
            o[3][6] += pf.w * v1.z; o[3][7] += pf.w * v1.w;
        }
    }

    // Epilogue: O / l
    #pragma unroll
    for (int i = 0; i < 4; i++) {
        float inv = 1.0f / lrow[i];
        float4 a = make_float4(o[i][0] * inv, o[i][1] * inv,
                               o[i][2] * inv, o[i][3] * inv);
        float4 b = make_float4(o[i][4] * inv, o[i][5] * inv,
                               o[i][6] * inv, o[i][7] * inv);
        *(float4*)&Ag[(tr * 4 + i) * HD + tc * 8]     = a;
        *(float4*)&Ag[(tr * 4 + i) * HD + tc * 8 + 4] = b;
    }
}

// ---------------------------------------------------------------------------
// Kernel C: final FC.  att reshaped [S,B,E] is the same flat buffer g_Att;
// out[r][o] = sum_e X[r][e] * Wfc[o][e] + bfc[o], r in [0,4096), o in [0,512).
// 64x64 output tiles, BK=32, 256 threads, 4x4 microtile.
// grid: (4096/64, 512/64), block: 256
// ---------------------------------------------------------------------------
constexpr int FBK  = 32;
constexpr int FSTR = 68;

__global__ __launch_bounds__(256) void fc_kernel(
    const float* __restrict__ Wfc, const float* __restrict__ bfc,
    float* __restrict__ out)
{
    __shared__ float Xs [FBK * FSTR];   // [k][m]
    __shared__ float Ws2[FBK * FSTR];   // [k][n]

    int r0  = blockIdx.x * 64;
    int n0  = blockIdx.y * 64;
    int tid = threadIdx.x;
    int tr  = tid >> 4;     // 0..15
    int tc  = tid & 15;     // 0..15

    float acc[4][4];
    #pragma unroll
    for (int i = 0; i < 4; i++)
        #pragma unroll
        for (int j = 0; j < 4; j++) acc[i][j] = 0.f;

    for (int e0 = 0; e0 < EMB; e0 += FBK) {
        __syncthreads();
        #pragma unroll
        for (int i = 0; i < 2; i++) {
            int f4 = tid + i * 256;       // 0..511
            int r  = f4 >> 3;
            int e4 = (f4 & 7) * 4;
            float4 val = *(const float4*)&g_Att[(size_t)(r0 + r) * EMB + e0 + e4];
            Xs[(e4 + 0) * FSTR + r] = val.x;
            Xs[(e4 + 1) * FSTR + r] = val.y;
            Xs[(e4 + 2) * FSTR + r] = val.z;
            Xs[(e4 + 3) * FSTR + r] = val.w;
        }
        #pragma unroll
        for (int i = 0; i < 2; i++) {
            int f4 = tid + i * 256;
            int n  = f4 >> 3;
            int e4 = (f4 & 7) * 4;
            float4 val = *(const float4*)&Wfc[(size_t)(n0 + n) * EMB + e0 + e4];
            Ws2[(e4 + 0) * FSTR + n] = val.x;
            Ws2[(e4 + 1) * FSTR + n] = val.y;
            Ws2[(e4 + 2) * FSTR + n] = val.z;
            Ws2[(e4 + 3) * FSTR + n] = val.w;
        }
        __syncthreads();

        #pragma unroll 8
        for (int kk = 0; kk < FBK; kk++) {
            float4 xf = *(const float4*)&Xs [kk * FSTR + tr * 4];
            float4 wf = *(const float4*)&Ws2[kk * FSTR + tc * 4];
            acc[0][0] += xf.x * wf.x; acc[0][1] += xf.x * wf.y;
            acc[0][2] += xf.x * wf.z; acc[0][3] += xf.x * wf.w;
            acc[1][0] += xf.y * wf.x; acc[1][1] += xf.y * wf.y;
            acc[1][2] += xf.y * wf.z; acc[1][3] += xf.y * wf.w;
            acc[2][0] += xf.z * wf.x; acc[2][1] += xf.z * wf.y;
            acc[2][2] += xf.z * wf.z; acc[2][3] += xf.z * wf.w;
            acc[3][0] += xf.w * wf.x; acc[3][1] += xf.w * wf.y;
            acc[3][2] += xf.w * wf.z; acc[3][3] += xf.w * wf.w;
        }
    }

    float4 bv = *(const float4*)&bfc[n0 + tc * 4];
    #pragma unroll
    for (int i = 0; i < 4; i++) {
        float4 val = make_float4(acc[i][0] + bv.x, acc[i][1] + bv.y,
                                 acc[i][2] + bv.z, acc[i][3] + bv.w);
        *(float4*)&out[(size_t)(r0 + tr * 4 + i) * EMB + n0 + tc * 4] = val;
    }
}

// ---------------------------------------------------------------------------
extern "C" void kernel_launch(void* const* d_in, const int* in_sizes, int n_in,
                              void* d_out, int out_size)
{
    const float* q   = (const float*)d_in[0];
    const float* k   = (const float*)d_in[1];
    const float* v   = (const float*)d_in[2];
    const float* Wq  = (const float*)d_in[3];
    const float* Wk  = (const float*)d_in[4];
    const float* Wv  = (const float*)d_in[5];
    const float* Wfc = (const float*)d_in[6];
    const float* bfc = (const float*)d_in[7];
    float* out = (float*)d_out;

    dim3 gA(S_LEN / 64, NBH, 3);
    proj_kernel<<<gA, 256>>>(q, k, v, Wq, Wk, Wv);

    dim3 gB(S_LEN / BM, NBH);
    flash_kernel<<<gB, 128>>>();

    dim3 gC(NTOK / 64, EMB / 64);
    fc_kernel<<<gC, 256>>>(Wfc, bfc, out);
}

// round 5
// speedup vs baseline: 1.5529x; 1.5529x over previous
#include <cuda_runtime.h>

// ---------------------------------------------------------------------------
// Problem constants
// ---------------------------------------------------------------------------
constexpr int S_LEN = 2048;
constexpr int BATCH = 2;
constexpr int EMB   = 512;
constexpr int HEADS = 8;
constexpr int HD    = 64;               // head dim
constexpr int NBH   = BATCH * HEADS;    // 16
constexpr int NTOK  = S_LEN * BATCH;    // 4096 rows for the final FC

// Scratch (device globals: no allocation allowed)
__device__ float g_Q[NBH * S_LEN * HD];
__device__ float g_K[NBH * S_LEN * HD];
__device__ float g_V[NBH * S_LEN * HD];
__device__ float g_Att[NBH * S_LEN * HD];

// ---------------------------------------------------------------------------
// Kernel A: QKV projection.  qh is a flat-contiguous [16][2048][64] view.
// y[bh][s][o] = sum_d x[bh][s][d] * W[o][d]   (torch Linear: x @ W.T)
// Q additionally scaled by 1/sqrt(64) = 0.125 (folds the softmax scale).
// grid: (S/64, 16, 3), block: 256
// ---------------------------------------------------------------------------
__global__ __launch_bounds__(256) void proj_kernel(
    const float* __restrict__ q, const float* __restrict__ k,
    const float* __restrict__ v,
    const float* __restrict__ Wq, const float* __restrict__ Wk,
    const float* __restrict__ Wv)
{
    __shared__ float Ws[HD * HD];       // [o][d]
    __shared__ float Xs[64][HD + 1];    // padded vs bank conflicts

    const float* in;  const float* W;  float* out;  float scale;
    int z = blockIdx.z;
    if (z == 0)      { in = q; W = Wq; out = g_Q; scale = 0.125f; }
    else if (z == 1) { in = k; W = Wk; out = g_K; scale = 1.0f; }
    else             { in = v; W = Wv; out = g_V; scale = 1.0f; }

    int bh = blockIdx.y;
    int r0 = blockIdx.x * 64;
    const float* inb  = in  + (size_t)bh * S_LEN * HD + (size_t)r0 * HD;
    float*       outb = out + (size_t)bh * S_LEN * HD + (size_t)r0 * HD;
    int tid = threadIdx.x;

    // Load W (4096 floats) and X tile (64x64), both contiguous in gmem.
    #pragma unroll
    for (int i = 0; i < 4; i++)
        ((float4*)Ws)[tid + i * 256] = ((const float4*)W)[tid + i * 256];
    #pragma unroll
    for (int i = 0; i < 4; i++) {
        int f4 = tid + i * 256;           // 0..1023
        int r  = f4 >> 4;
        int d0 = (f4 & 15) * 4;
        float4 val = ((const float4*)inb)[f4];
        Xs[r][d0 + 0] = val.x;  Xs[r][d0 + 1] = val.y;
        Xs[r][d0 + 2] = val.z;  Xs[r][d0 + 3] = val.w;
    }
    __syncthreads();

    int r  = tid & 63;
    int c0 = (tid >> 6) * 16;             // 4 groups of 16 output cols
    float acc[16];
    #pragma unroll
    for (int j = 0; j < 16; j++) acc[j] = 0.f;

    #pragma unroll 8
    for (int d = 0; d < HD; d++) {
        float xv = Xs[r][d];
        #pragma unroll
        for (int j = 0; j < 16; j++)
            acc[j] += xv * Ws[(c0 + j) * HD + d];   // broadcast LDS
    }

    #pragma unroll
    for (int j = 0; j < 16; j += 4) {
        float4 val = make_float4(acc[j] * scale, acc[j + 1] * scale,
                                 acc[j + 2] * scale, acc[j + 3] * scale);
        *(float4*)&outb[r * HD + c0 + j] = val;
    }
}

// ---------------------------------------------------------------------------
// Kernel B: flash attention per (bh), BM=64 query rows per block, BN=32 key
// tiles, 128 threads (tr 0..15, tc 0..7), 4x4 score microtile, 4x8 O microtile.
// Smem layouts transposed so fragments are float4 loads.
// grid: (S/64, 16), block: 128
// ---------------------------------------------------------------------------
constexpr int BM = 64;
constexpr int BN = 32;
constexpr int QS_STR = 68;   // [d][m], padded
constexpr int KS_STR = 36;   // [d][n], padded
constexpr int PS_STR = 68;   // [n][m], padded

__global__ __launch_bounds__(128) void flash_kernel()
{
    __shared__ float Qs[HD * QS_STR];    // 17408 B
    __shared__ float Ks[HD * KS_STR];    //  9216 B
    __shared__ float Vs[BN * HD];        //  8192 B  [n][d]
    __shared__ float Ps[BN * PS_STR];    //  8704 B  [n][m]

    int bh  = blockIdx.y;
    int m0  = blockIdx.x * BM;
    int tid = threadIdx.x;
    int tr  = tid >> 3;      // 0..15 -> 4 query rows each
    int tc  = tid & 7;       // 0..7

    const float* Qg = g_Q + (size_t)bh * S_LEN * HD + (size_t)m0 * HD;
    const float* Kg = g_K + (size_t)bh * S_LEN * HD;
    const float* Vg = g_V + (size_t)bh * S_LEN * HD;
    float*       Ag = g_Att + (size_t)bh * S_LEN * HD + (size_t)m0 * HD;

    // Load Q tile (64x64, contiguous) transposed into Qs[d][m].
    #pragma unroll
    for (int i = 0; i < 8; i++) {
        int f4 = tid + i * 128;          // 0..1023
        int r  = f4 >> 4;
        int d0 = (f4 & 15) * 4;
        float4 val = ((const float4*)Qg)[f4];
        Qs[(d0 + 0) * QS_STR + r] = val.x;
        Qs[(d0 + 1) * QS_STR + r] = val.y;
        Qs[(d0 + 2) * QS_STR + r] = val.z;
        Qs[(d0 + 3) * QS_STR + r] = val.w;
    }

    float o[4][8];
    float mrow[4], lrow[4];
    #pragma unroll
    for (int i = 0; i < 4; i++) {
        mrow[i] = -1e30f; lrow[i] = 0.f;
        #pragma unroll
        for (int j = 0; j < 8; j++) o[i][j] = 0.f;
    }

    for (int n0 = 0; n0 < S_LEN; n0 += BN) {
        __syncthreads();   // prior P@V done before overwriting Ks/Vs
        // K tile (32x64, contiguous) transposed into Ks[d][n]
        #pragma unroll
        for (int i = 0; i < 4; i++) {
            int f4 = tid + i * 128;       // 0..511
            int n  = f4 >> 4;
            int d0 = (f4 & 15) * 4;
            float4 val = ((const float4*)(Kg + (size_t)n0 * HD))[f4];
            Ks[(d0 + 0) * KS_STR + n] = val.x;
            Ks[(d0 + 1) * KS_STR + n] = val.y;
            Ks[(d0 + 2) * KS_STR + n] = val.z;
            Ks[(d0 + 3) * KS_STR + n] = val.w;
        }
        // V tile: straight copy [n][d]
        #pragma unroll
        for (int i = 0; i < 4; i++) {
            int f4 = tid + i * 128;
            ((float4*)Vs)[f4] = ((const float4*)(Vg + (size_t)n0 * HD))[f4];
        }
        __syncthreads();

        // S = Q K^T  (scale already folded into Q)
        float s[4][4];
        #pragma unroll
        for (int i = 0; i < 4; i++)
            #pragma unroll
            for (int j = 0; j < 4; j++) s[i][j] = 0.f;

        #pragma unroll 8
        for (int d = 0; d < HD; d++) {
            float4 qf = *(const float4*)&Qs[d * QS_STR + tr * 4];
            float4 kf = *(const float4*)&Ks[d * KS_STR + tc * 4];
            s[0][0] += qf.x * kf.x; s[0][1] += qf.x * kf.y;
            s[0][2] += qf.x * kf.z; s[0][3] += qf.x * kf.w;
            s[1][0] += qf.y * kf.x; s[1][1] += qf.y * kf.y;
            s[1][2] += qf.y * kf.z; s[1][3] += qf.y * kf.w;
            s[2][0] += qf.z * kf.x; s[2][1] += qf.z * kf.y;
            s[2][2] += qf.z * kf.z; s[2][3] += qf.z * kf.w;
            s[3][0] += qf.w * kf.x; s[3][1] += qf.w * kf.y;
            s[3][2] += qf.w * kf.z; s[3][3] += qf.w * kf.w;
        }

        // Online softmax (row groups = 8 lanes: tc bits 0..2)
        #pragma unroll
        for (int i = 0; i < 4; i++) {
            float mx = fmaxf(fmaxf(s[i][0], s[i][1]), fmaxf(s[i][2], s[i][3]));
            mx = fmaxf(mx, __shfl_xor_sync(0xffffffffu, mx, 1));
            mx = fmaxf(mx, __shfl_xor_sync(0xffffffffu, mx, 2));
            mx = fmaxf(mx, __shfl_xor_sync(0xffffffffu, mx, 4));
            float mnew = fmaxf(mrow[i], mx);
            float corr = __expf(mrow[i] - mnew);
            mrow[i] = mnew;
            float rs = 0.f;
            #pragma unroll
            for (int j = 0; j < 4; j++) {
                s[i][j] = __expf(s[i][j] - mnew);
                rs += s[i][j];
            }
            rs += __shfl_xor_sync(0xffffffffu, rs, 1);
            rs += __shfl_xor_sync(0xffffffffu, rs, 2);
            rs += __shfl_xor_sync(0xffffffffu, rs, 4);
            lrow[i] = lrow[i] * corr + rs;
            #pragma unroll
            for (int j = 0; j < 8; j++) o[i][j] *= corr;
        }

        // Store P transposed: Ps[n][m]
        #pragma unroll
        for (int j = 0; j < 4; j++)
            #pragma unroll
            for (int i = 0; i < 4; i++)
                Ps[(tc * 4 + j) * PS_STR + tr * 4 + i] = s[i][j];
        __syncthreads();

        // O += P V   (thread: 4 rows x 8 d-cols)
        #pragma unroll 4
        for (int n = 0; n < BN; n++) {
            float4 pf = *(const float4*)&Ps[n * PS_STR + tr * 4];
            float4 v0 = *(const float4*)&Vs[n * HD + tc * 8];
            float4 v1 = *(const float4*)&Vs[n * HD + tc * 8 + 4];
            o[0][0] += pf.x * v0.x; o[0][1] += pf.x * v0.y;
            o[0][2] += pf.x * v0.z; o[0][3] += pf.x * v0.w;
            o[0][4] += pf.x * v1.x; o[0][5] += pf.x * v1.y;
            o[0][6] += pf.x * v1.z; o[0][7] += pf.x * v1.w;
            o[1][0] += pf.y * v0.x; o[1][1] += pf.y * v0.y;
            o[1][2] += pf.y * v0.z; o[1][3] += pf.y * v0.w;
            o[1][4] += pf.y * v1.x; o[1][5] += pf.y * v1.y;
            o[1][6] += pf.y * v1.z; o[1][7] += pf.y * v1.w;
            o[2][0] += pf.z * v0.x; o[2][1] += pf.z * v0.y;
            o[2][2] += pf.z * v0.z; o[2][3] += pf.z * v0.w;
            o[2][4] += pf.z * v1.x; o[2][5] += pf.z * v1.y;
            o[2][6] += pf.z * v1.z; o[2][7] += pf.z * v1.w;
            o[3][0] += pf.w * v0.x; o[3][1] += pf.w * v0.y;
            o[3][2] += pf.w * v0.z; o[3][3] += pf.w * v0.w;
            o[3][4] += pf.w * v1.x; o[3][5] += pf.w * v1.y;
            o[3][6] += pf.w * v1.z; o[3][7] += pf.w * v1.w;
        }
    }

    // Epilogue: O / l
    #pragma unroll
    for (int i = 0; i < 4; i++) {
        float inv = 1.0f / lrow[i];
        float4 a = make_float4(o[i][0] * inv, o[i][1] * inv,
                               o[i][2] * inv, o[i][3] * inv);
        float4 b = make_float4(o[i][4] * inv, o[i][5] * inv,
                               o[i][6] * inv, o[i][7] * inv);
        *(float4*)&Ag[(tr * 4 + i) * HD + tc * 8]     = a;
        *(float4*)&Ag[(tr * 4 + i) * HD + tc * 8 + 4] = b;
    }
}

// ---------------------------------------------------------------------------
// Kernel C: final FC.  att reshaped [S,B,E] is the same flat buffer g_Att;
// out[r][o] = sum_e X[r][e] * Wfc[o][e] + bfc[o], r in [0,4096), o in [0,512).
// 64x64 output tiles, BK=32, 256 threads, 4x4 microtile.
// grid: (4096/64, 512/64), block: 256
// ---------------------------------------------------------------------------
constexpr int FBK  = 32;
constexpr int FSTR = 68;

__global__ __launch_bounds__(256) void fc_kernel(
    const float* __restrict__ Wfc, const float* __restrict__ bfc,
    float* __restrict__ out)
{
    __shared__ float Xs [FBK * FSTR];   // [k][m]
    __shared__ float Ws2[FBK * FSTR];   // [k][n]

    int r0  = blockIdx.x * 64;
    int n0  = blockIdx.y * 64;
    int tid = threadIdx.x;
    int tr  = tid >> 4;     // 0..15
    int tc  = tid & 15;     // 0..15

    float acc[4][4];
    #pragma unroll
    for (int i = 0; i < 4; i++)
        #pragma unroll
        for (int j = 0; j < 4; j++) acc[i][j] = 0.f;

    for (int e0 = 0; e0 < EMB; e0 += FBK) {
        __syncthreads();
        #pragma unroll
        for (int i = 0; i < 2; i++) {
            int f4 = tid + i * 256;       // 0..511
            int r  = f4 >> 3;
            int e4 = (f4 & 7) * 4;
            float4 val = *(const float4*)&g_Att[(size_t)(r0 + r) * EMB + e0 + e4];
            Xs[(e4 + 0) * FSTR + r] = val.x;
            Xs[(e4 + 1) * FSTR + r] = val.y;
            Xs[(e4 + 2) * FSTR + r] = val.z;
            Xs[(e4 + 3) * FSTR + r] = val.w;
        }
        #pragma unroll
        for (int i = 0; i < 2; i++) {
            int f4 = tid + i * 256;
            int n  = f4 >> 3;
            int e4 = (f4 & 7) * 4;
            float4 val = *(const float4*)&Wfc[(size_t)(n0 + n) * EMB + e0 + e4];
            Ws2[(e4 + 0) * FSTR + n] = val.x;
            Ws2[(e4 + 1) * FSTR + n] = val.y;
            Ws2[(e4 + 2) * FSTR + n] = val.z;
            Ws2[(e4 + 3) * FSTR + n] = val.w;
        }
        __syncthreads();

        #pragma unroll 8
        for (int kk = 0; kk < FBK; kk++) {
            float4 xf = *(const float4*)&Xs [kk * FSTR + tr * 4];
            float4 wf = *(const float4*)&Ws2[kk * FSTR + tc * 4];
            acc[0][0] += xf.x * wf.x; acc[0][1] += xf.x * wf.y;
            acc[0][2] += xf.x * wf.z; acc[0][3] += xf.x * wf.w;
            acc[1][0] += xf.y * wf.x; acc[1][1] += xf.y * wf.y;
            acc[1][2] += xf.y * wf.z; acc[1][3] += xf.y * wf.w;
            acc[2][0] += xf.z * wf.x; acc[2][1] += xf.z * wf.y;
            acc[2][2] += xf.z * wf.z; acc[2][3] += xf.z * wf.w;
            acc[3][0] += xf.w * wf.x; acc[3][1] += xf.w * wf.y;
            acc[3][2] += xf.w * wf.z; acc[3][3] += xf.w * wf.w;
        }
    }

    float4 bv = *(const float4*)&bfc[n0 + tc * 4];
    #pragma unroll
    for (int i = 0; i < 4; i++) {
        float4 val = make_float4(acc[i][0] + bv.x, acc[i][1] + bv.y,
                                 acc[i][2] + bv.z, acc[i][3] + bv.w);
        *(float4*)&out[(size_t)(r0 + tr * 4 + i) * EMB + n0 + tc * 4] = val;
    }
}

// ---------------------------------------------------------------------------
extern "C" void kernel_launch(void* const* d_in, const int* in_sizes, int n_in,
                              void* d_out, int out_size)
{
    const float* q   = (const float*)d_in[0];
    const float* k   = (const float*)d_in[1];
    const float* v   = (const float*)d_in[2];
    const float* Wq  = (const float*)d_in[3];
    const float* Wk  = (const float*)d_in[4];
    const float* Wv  = (const float*)d_in[5];
    const float* Wfc = (const float*)d_in[6];
    const float* bfc = (const float*)d_in[7];
    float* out = (float*)d_out;

    dim3 gA(S_LEN / 64, NBH, 3);
    proj_kernel<<<gA, 256>>>(q, k, v, Wq, Wk, Wv);

    dim3 gB(S_LEN / BM, NBH);
    flash_kernel<<<gB, 128>>>();

    dim3 gC(NTOK / 64, EMB / 64);
    fc_kernel<<<gC, 256>>>(Wfc, bfc, out);
}